// round 4
// baseline (speedup 1.0000x reference)
#include <cuda_runtime.h>
#include <cuda_bf16.h>

#define BB 512
#define TT 512
#define LL 64

__device__ float g_res[BB];
__device__ unsigned int g_done = 0;   // last-CTA-done counter (self-resetting)

__global__ void __launch_bounds__(64) crf_main_kernel(
    const float* __restrict__ emission,   // [B,T,L]
    const int*   __restrict__ target,     // [B,T]
    const float* __restrict__ mask,       // [B,T]
    const float* __restrict__ start_trans,// [L]
    const float* __restrict__ trans,      // [L,L]
    const float* __restrict__ end_trans,  // [L]
    float* __restrict__ out)
{
    __shared__ float sm_m[TT + 1];
    __shared__ float sm_e[TT];
    __shared__ __align__(16) float sm_p[2][LL];
    __shared__ float sm_s0[2];
    __shared__ float sm_red[2];
    __shared__ float sm_x[2];
    __shared__ unsigned int sm_last;

    const int b    = blockIdx.x;
    const int j    = threadIdx.x;      // label index 0..63
    const int warp = j >> 5;
    const int lane = j & 31;

    const float* emb = emission + (size_t)b * TT * LL;
    const int*   tgt = target   + (size_t)b * TT;

    // stage mask row into shared
    for (int t = j; t < TT; t += 64) sm_m[t] = mask[(size_t)b * TT + t];
    if (j == 0) sm_m[TT] = 0.0f;

    // E column j in registers: E[i][j] = exp(trans[i][j])
    float Ecol[LL];
    #pragma unroll
    for (int i = 0; i < LL; i++) Ecol[i] = __expf(trans[i * LL + j]);
    __syncthreads();

    // end-mask per timestep
    for (int t = j; t < TT; t += 64)
        sm_e[t] = (sm_m[t] > sm_m[t + 1]) ? 1.0f : 0.0f;
    __syncthreads();

    // ---------------- path score: parallel reduction over t ----------------
    float pacc = 0.0f;
    for (int t = 1 + j; t < TT; t += 64) {
        int tp = tgt[t - 1];
        int tc = tgt[t];
        pacc += sm_m[t] * (trans[tp * LL + tc] + emb[(size_t)t * LL + tc])
              + sm_e[t] * end_trans[tc];
    }
    if (j == 0) {
        int t0 = tgt[0];
        pacc += start_trans[t0] + emb[t0];
    }
    #pragma unroll
    for (int o = 16; o; o >>= 1) pacc += __shfl_xor_sync(0xffffffffu, pacc, o);
    if (lane == 0) sm_x[warp] = pacc;
    __syncthreads();
    const float path_score = sm_x[0] + sm_x[1];

    // ---------------- forward recursion (normalizer) ----------------
    const float et = end_trans[j];
    float s = start_trans[j] + emb[j];          // t = 0

    if (j == 0) sm_s0[1] = s;
    __syncthreads();
    float S = sm_s0[1];

    // emission prefetch, distance 2
    float em1 = emb[1 * LL + j];
    float em2 = emb[2 * LL + j];

    for (int t = 1; t < TT; t++) {
        const int buf = t & 1;
        const float em_cur = em1;
        em1 = em2;
        if (t + 2 < TT) em2 = emb[(size_t)(t + 2) * LL + j];

        if (j == 0) sm_s0[buf] = s;             // shift for next iteration (STS first)
        sm_p[buf][j] = __expf(s - S);           // stabilized prob
        __syncthreads();

        // dot_j = sum_i p_i * E[i][j]   (8 accumulators -> 8-deep chains)
        const float4* p4 = (const float4*)sm_p[buf];
        float a0 = 0.f, a1 = 0.f, a2 = 0.f, a3 = 0.f;
        float a4 = 0.f, a5 = 0.f, a6 = 0.f, a7 = 0.f;
        #pragma unroll
        for (int i = 0; i < LL / 8; i++) {
            const float4 vA = p4[2 * i];
            const float4 vB = p4[2 * i + 1];
            a0 += vA.x * Ecol[8 * i + 0];
            a1 += vA.y * Ecol[8 * i + 1];
            a2 += vA.z * Ecol[8 * i + 2];
            a3 += vA.w * Ecol[8 * i + 3];
            a4 += vB.x * Ecol[8 * i + 4];
            a5 += vB.y * Ecol[8 * i + 5];
            a6 += vB.z * Ecol[8 * i + 6];
            a7 += vB.w * Ecol[8 * i + 7];
        }
        const float dot = ((a0 + a1) + (a2 + a3)) + ((a4 + a5) + (a6 + a7));

        const float nxt = S + __logf(dot) + em_cur;
        const float m   = sm_m[t];
        s = m * nxt + (1.0f - m) * s + sm_e[t] * et;

        S = sm_s0[buf];
    }

    // normalizer = logsumexp_j(s)
    float wm = s;
    #pragma unroll
    for (int o = 16; o; o >>= 1) wm = fmaxf(wm, __shfl_xor_sync(0xffffffffu, wm, o));
    if (lane == 0) sm_red[warp] = wm;
    __syncthreads();
    const float M = fmaxf(sm_red[0], sm_red[1]);
    float pe = __expf(s - M);
    #pragma unroll
    for (int o = 16; o; o >>= 1) pe += __shfl_xor_sync(0xffffffffu, pe, o);
    if (lane == 0) sm_x[warp] = pe;
    __syncthreads();

    // ---------------- fused deterministic finalization ----------------
    if (j == 0) {
        const float norm = M + __logf(sm_x[0] + sm_x[1]);
        g_res[b] = norm - path_score;
        __threadfence();
        sm_last = atomicAdd(&g_done, 1u);       // returns BB-1 for the last CTA
    }
    __syncthreads();
    if (sm_last == BB - 1) {
        __threadfence();                        // acquire: see all g_res writes
        // fixed-order deterministic sum: thread j sums rows j, j+64, ...
        float acc = 0.0f;
        #pragma unroll
        for (int k = 0; k < BB / 64; k++) acc += g_res[j + k * 64];
        #pragma unroll
        for (int o = 16; o; o >>= 1) acc += __shfl_xor_sync(0xffffffffu, acc, o);
        if (lane == 0) sm_red[warp] = acc;
        __syncthreads();
        if (j == 0) {
            out[0] = (sm_red[0] + sm_red[1]) * (1.0f / BB);
            g_done = 0;                         // reset for next graph replay
        }
    }
}

extern "C" void kernel_launch(void* const* d_in, const int* in_sizes, int n_in,
                              void* d_out, int out_size) {
    const float* emission    = (const float*)d_in[0];
    const int*   target      = (const int*)  d_in[1];
    const float* mask        = (const float*)d_in[2];
    const float* start_trans = (const float*)d_in[3];
    const float* trans       = (const float*)d_in[4];
    const float* end_trans   = (const float*)d_in[5];
    float* out = (float*)d_out;

    crf_main_kernel<<<BB, 64>>>(emission, target, mask, start_trans, trans,
                                end_trans, out);
}

// round 5
// speedup vs baseline: 1.0918x; 1.0918x over previous
#include <cuda_runtime.h>
#include <cuda_bf16.h>

#define BB 512
#define TT 512
#define LL 64

__device__ float g_res[BB];
__device__ unsigned int g_done = 0;   // last-CTA ticket (self-resetting)

__global__ void __launch_bounds__(32) crf_main_kernel(
    const float* __restrict__ emission,   // [B,T,L]
    const int*   __restrict__ target,     // [B,T]
    const float* __restrict__ mask,       // [B,T]
    const float* __restrict__ start_trans,// [L]
    const float* __restrict__ trans,      // [L,L]
    const float* __restrict__ end_trans,  // [L]
    float* __restrict__ out)
{
    __shared__ float2 sm_me[TT];                 // (mask_t, endmask_t)
    __shared__ __align__(16) float sm_p[2][LL];  // double-buffered probs
    __shared__ unsigned int sm_last;

    const int b    = blockIdx.x;
    const int lane = threadIdx.x;                // 0..31
    const int jA   = 2 * lane;                   // labels owned by this lane
    // jB = jA + 1

    const float*  emb  = emission + (size_t)b * TT * LL;
    const float2* emb2 = (const float2*)emb;     // float2 idx: t*32 + lane
    const int*    tgt  = target   + (size_t)b * TT;
    const float*  mrow = mask     + (size_t)b * TT;

    // stage (mask, end_mask) pairs
    for (int t = lane; t < TT; t += 32) {
        float m  = mrow[t];
        float nm = (t + 1 < TT) ? mrow[t + 1] : 0.0f;
        sm_me[t] = make_float2(m, (m > nm) ? 1.0f : 0.0f);
    }

    // E columns jA, jB in registers: E[i][j] = exp(trans[i][j])
    float EA[LL], EB[LL];
    #pragma unroll
    for (int i = 0; i < LL; i++) {
        const float2 tr = ((const float2*)trans)[i * 32 + lane];
        EA[i] = __expf(tr.x);
        EB[i] = __expf(tr.y);
    }
    __syncwarp();

    // ---------------- path score: parallel reduction over t ----------------
    float pacc = 0.0f;
    for (int t = 1 + lane; t < TT; t += 32) {
        const int    tp = tgt[t - 1];
        const int    tc = tgt[t];
        const float2 me = sm_me[t];
        pacc += me.x * (trans[tp * LL + tc] + emb[(size_t)t * LL + tc])
              + me.y * end_trans[tc];
    }
    if (lane == 0) {
        const int t0 = tgt[0];
        pacc += start_trans[t0] + emb[t0];
    }
    #pragma unroll
    for (int o = 16; o; o >>= 1) pacc += __shfl_xor_sync(0xffffffffu, pacc, o);
    const float path_score = pacc;               // identical in all lanes

    // ---------------- forward recursion (normalizer) ----------------
    const float2 st2 = ((const float2*)start_trans)[lane];
    const float2 et2 = ((const float2*)end_trans)[lane];
    const float2 em0 = emb2[lane];
    float sA = st2.x + em0.x;                    // t = 0 scores
    float sB = st2.y + em0.y;

    float S = __shfl_sync(0xffffffffu, sA, 0);   // block-uniform shift (label 0)

    // emission prefetch, distance 2
    float2 em1 = emb2[1 * 32 + lane];
    float2 em2 = emb2[2 * 32 + lane];

    for (int t = 1; t < TT; t++) {
        const int    buf    = t & 1;
        const float2 em_cur = em1;
        em1 = em2;
        if (t + 2 < TT) em2 = emb2[(size_t)(t + 2) * 32 + lane];

        // stabilized probs (lagged uniform shift S)
        const float pA = __expf(sA - S);
        const float pB = __expf(sB - S);
        ((float2*)sm_p[buf])[lane] = make_float2(pA, pB);
        __syncwarp();

        // dot_j = sum_i p_i * E[i][j] for j = jA, jB
        const float4* p4 = (const float4*)sm_p[buf];
        float a0 = 0.f, a1 = 0.f, a2 = 0.f, a3 = 0.f;
        float b0 = 0.f, b1 = 0.f, b2 = 0.f, b3 = 0.f;
        #pragma unroll
        for (int i = 0; i < LL / 4; i++) {
            const float4 v = p4[i];
            a0 += v.x * EA[4 * i + 0];
            a1 += v.y * EA[4 * i + 1];
            a2 += v.z * EA[4 * i + 2];
            a3 += v.w * EA[4 * i + 3];
            b0 += v.x * EB[4 * i + 0];
            b1 += v.y * EB[4 * i + 1];
            b2 += v.z * EB[4 * i + 2];
            b3 += v.w * EB[4 * i + 3];
        }
        const float dotA = (a0 + a1) + (a2 + a3);
        const float dotB = (b0 + b1) + (b2 + b3);

        const float2 me  = sm_me[t];
        const float nxtA = S + __logf(dotA) + em_cur.x;
        const float nxtB = S + __logf(dotB) + em_cur.y;
        sA = me.x * nxtA + (1.0f - me.x) * sA + me.y * et2.x;
        sB = me.x * nxtB + (1.0f - me.x) * sB + me.y * et2.y;

        S = __shfl_sync(0xffffffffu, sA, 0);     // next iteration's shift
    }

    // normalizer = logsumexp over 64 labels (exact max; once)
    float wm = fmaxf(sA, sB);
    #pragma unroll
    for (int o = 16; o; o >>= 1) wm = fmaxf(wm, __shfl_xor_sync(0xffffffffu, wm, o));
    float pe = __expf(sA - wm) + __expf(sB - wm);
    #pragma unroll
    for (int o = 16; o; o >>= 1) pe += __shfl_xor_sync(0xffffffffu, pe, o);

    // ---------------- fused deterministic finalization ----------------
    if (lane == 0) {
        const float norm = wm + __logf(pe);
        g_res[b] = norm - path_score;
        __threadfence();
        sm_last = atomicAdd(&g_done, 1u);        // BB-1 for the last CTA
    }
    __syncwarp();
    if (sm_last == BB - 1) {
        __threadfence();                         // acquire all g_res
        float acc = 0.0f;
        #pragma unroll
        for (int k = 0; k < BB / 32; k++) acc += g_res[lane + k * 32];
        #pragma unroll
        for (int o = 16; o; o >>= 1) acc += __shfl_xor_sync(0xffffffffu, acc, o);
        if (lane == 0) {
            out[0] = acc * (1.0f / BB);
            g_done = 0;                          // reset for graph replay
        }
    }
}

extern "C" void kernel_launch(void* const* d_in, const int* in_sizes, int n_in,
                              void* d_out, int out_size) {
    const float* emission    = (const float*)d_in[0];
    const int*   target      = (const int*)  d_in[1];
    const float* mask        = (const float*)d_in[2];
    const float* start_trans = (const float*)d_in[3];
    const float* trans       = (const float*)d_in[4];
    const float* end_trans   = (const float*)d_in[5];
    float* out = (float*)d_out;

    crf_main_kernel<<<BB, 32>>>(emission, target, mask, start_trans, trans,
                                end_trans, out);
}